// round 14
// baseline (speedup 1.0000x reference)
#include <cuda_runtime.h>
#include <cuda_bf16.h>
#include <cstdint>

// RBF kernel matrix: out[i,j] = v * exp(cross_ij - hx_i - hy_j)
// cross via classic mma.sync m16n8k16 bf16, 3-term hi/lo split
// (hi*hi + hi*lo + lo*hi). N = M = 8192, D = 64. Output fp32 [N, M].
// R12: PERSISTENT strip kernel. 592 CTAs (=148 SM x 4), each walks ~14
// consecutive 64x128 tiles sharing one resident Y tile; X tile for t+1
// is cp.async'd under epilogue t. One wave -> no wave-transition tax,
// Y smem refill amortized 14x.

#define NROWS 8192
#define MROWS 8192
#define DDIM  64
#define NCTAS 592
#define XTILES 128                     // 8192/64 x-tiles per strip
#define TOTTILES 8192                  // 128 x * 64 y

// ---------------- device scratch (allocation-free rule) ----------------
__device__ float g_invl[DDIM];
__device__ float g_v;
__device__ float g_lv;                            // log2(v)
__device__ float g_hxn[NROWS];                    // 0.5*||Xl_i||^2
__device__ float g_hyn[MROWS];                    // 0.5*||X2l_j||^2
__device__ __nv_bfloat16 g_Xhi[NROWS * DDIM];
__device__ __nv_bfloat16 g_Xlo[NROWS * DDIM];
__device__ __nv_bfloat16 g_Yhi[MROWS * DDIM];
__device__ __nv_bfloat16 g_Ylo[MROWS * DDIM];

// ---------------- helpers ----------------
__device__ __forceinline__ uint32_t smem_u32(const void* p) {
    uint32_t a;
    asm("{ .reg .u64 t; cvta.to.shared.u64 t, %1; cvt.u32.u64 %0, t; }"
        : "=r"(a) : "l"(p));
    return a;
}

__device__ __forceinline__ void ldsm_x4(uint32_t& r0, uint32_t& r1,
                                        uint32_t& r2, uint32_t& r3,
                                        uint32_t addr) {
    asm volatile("ldmatrix.sync.aligned.m8n8.x4.shared.b16 {%0,%1,%2,%3}, [%4];"
                 : "=r"(r0), "=r"(r1), "=r"(r2), "=r"(r3) : "r"(addr));
}

__device__ __forceinline__ void mma_bf16(float* c, const uint32_t* a,
                                         uint32_t b0, uint32_t b1) {
    asm volatile(
        "mma.sync.aligned.m16n8k16.row.col.f32.bf16.bf16.f32 "
        "{%0,%1,%2,%3}, {%4,%5,%6,%7}, {%8,%9}, {%0,%1,%2,%3};"
        : "+f"(c[0]), "+f"(c[1]), "+f"(c[2]), "+f"(c[3])
        : "r"(a[0]), "r"(a[1]), "r"(a[2]), "r"(a[3]), "r"(b0), "r"(b1));
}

__device__ __forceinline__ float fexp2(float x) {
    float r;
    asm("ex2.approx.f32 %0, %1;" : "=f"(r) : "f"(x));
    return r;
}

#define CP_ASYNC16(dst, src) \
    asm volatile("cp.async.cg.shared.global [%0], [%1], 16;" \
                 :: "r"(dst), "l"(src) : "memory")
#define CP_COMMIT() asm volatile("cp.async.commit_group;" ::: "memory")
#define CP_WAIT0()  asm volatile("cp.async.wait_group 0;" ::: "memory")

// ---------------------------------------------------------------------------
// Prep: softplus params, bf16 hi/lo split of scaled rows, half squared norms
// ---------------------------------------------------------------------------
__global__ void prep_kernel(const float* __restrict__ X,
                            const float* __restrict__ X2,
                            const float* __restrict__ ls,
                            const float* __restrict__ var) {
    __shared__ float invl_s[DDIM];
    int t = threadIdx.x;
    if (t < DDIM) {
        float r = ls[t];
        float l = fmaxf(r, 0.0f) + log1pf(expf(-fabsf(r)));
        float il = 1.0f / l;
        invl_s[t] = il;
        if (blockIdx.x == 0) g_invl[t] = il;
    }
    if (blockIdx.x == 0 && t == 64) {
        float r = var[0];
        float v = fmaxf(r, 0.0f) + log1pf(expf(-fabsf(r)));
        g_v = v;
        g_lv = log2f(v);
    }
    __syncthreads();

    int warp = t >> 5, lane = t & 31;
    int nwarps = blockDim.x >> 5;
    for (int row = blockIdx.x * nwarps + warp; row < NROWS + MROWS;
         row += gridDim.x * nwarps) {
        const float* src;
        __nv_bfloat16 *hi, *lo;
        int r;
        bool isX = (row < NROWS);
        if (isX) { r = row;         src = X  + (size_t)r * DDIM; hi = g_Xhi; lo = g_Xlo; }
        else     { r = row - NROWS; src = X2 + (size_t)r * DDIM; hi = g_Yhi; lo = g_Ylo; }
        float s = 0.0f;
        #pragma unroll
        for (int j = 0; j < 2; j++) {
            int d = lane + 32 * j;
            float xl = src[d] * invl_s[d];
            __nv_bfloat16 bh = __float2bfloat16(xl);
            __nv_bfloat16 bl = __float2bfloat16(xl - __bfloat162float(bh));
            hi[(size_t)r * DDIM + d] = bh;
            lo[(size_t)r * DDIM + d] = bl;
            s = fmaf(xl, xl, s);
        }
        #pragma unroll
        for (int off = 16; off; off >>= 1)
            s += __shfl_xor_sync(0xffffffffu, s, off);
        if (lane == 0) {
            if (isX) g_hxn[r] = 0.5f * s;
            else     g_hyn[r] = 0.5f * s;
        }
    }
}

// ---------------------------------------------------------------------------
// Persistent main kernel.
// Tile = 64 (x rows) x 128 (y cols). 4 warps side by side along n (64x32
// each; mma m16n8k16, 4 mt x 4 nt x 3 terms x 4 k-chunks).
// Smem: HY(512B) | Xhi,Xlo (8KB each) | Yhi,Ylo (16KB each) = ~50KB.
// 16B-chunk XOR swizzle phys_chunk = c ^ (row & 7) -> ldmatrix
// conflict-free.
// ---------------------------------------------------------------------------
#define SMEM_HY    0                   // 128 floats: hy*L2E
#define SMEM_X     1024
#define XT_BYTES   8192                // 64 rows * 128B
#define SMEM_Y     (1024 + 2 * XT_BYTES)
#define YT_BYTES   16384               // 128 rows * 128B
#define SMEM_TOTAL (1024 + 2 * XT_BYTES + 2 * YT_BYTES)

__device__ __forceinline__ void load_x_tile(uint32_t sX, int x0, int t) {
    const uint4* s0 = (const uint4*)(g_Xhi + (size_t)x0 * DDIM);
    const uint4* s1 = (const uint4*)(g_Xlo + (size_t)x0 * DDIM);
    #pragma unroll
    for (int i = 0; i < 4; i++) {              // 512 chunks / 128 thr
        int id = t + i * 128;
        int row = id >> 3, c = id & 7;
        uint32_t sw = (uint32_t)row * 128 + (uint32_t)((c ^ (row & 7)) * 16);
        CP_ASYNC16(sX + sw, s0 + id);
        CP_ASYNC16(sX + XT_BYTES + sw, s1 + id);
    }
}

__device__ __forceinline__ void load_y_tile(uint32_t sY, int y0, int t) {
    const uint4* s0 = (const uint4*)(g_Yhi + (size_t)y0 * DDIM);
    const uint4* s1 = (const uint4*)(g_Ylo + (size_t)y0 * DDIM);
    #pragma unroll
    for (int i = 0; i < 8; i++) {              // 1024 chunks / 128 thr
        int id = t + i * 128;
        int row = id >> 3, c = id & 7;
        uint32_t sw = (uint32_t)row * 128 + (uint32_t)((c ^ (row & 7)) * 16);
        CP_ASYNC16(sY + sw, s0 + id);
        CP_ASYNC16(sY + YT_BYTES + sw, s1 + id);
    }
}

__global__ void __launch_bounds__(128, 4)
rbf_mma_kernel(float* __restrict__ out) {
    extern __shared__ char smem[];
    const uint32_t sb = smem_u32(smem);
    const int t = threadIdx.x;
    const int wid = t >> 5;
    const int lane = t & 31;
    const int cta = blockIdx.x;

    const float L2E = 1.4426950408889634f;
    const float lv = g_lv;

    // Tile range for this CTA: 8192 tiles over 592 CTAs (496x14 + 96x13).
    const int extra = (cta < 496) ? cta : 496;
    const int start = cta * 13 + extra;
    const int cnt = 13 + (cta < 496 ? 1 : 0);

    const uint32_t sX = sb + SMEM_X;
    const uint32_t sY = sb + SMEM_Y;
    float* HY = (float*)smem;

    // Prologue: X(tile0), Y(strip of tile0), HY.
    {
        int t0 = start;
        int x0 = (t0 & 127) * 64;
        int y0 = (t0 >> 7) * 128;
        load_x_tile(sX, x0, t);
        load_y_tile(sY, y0, t);
        CP_COMMIT();
        HY[t] = g_hyn[y0 + t] * L2E;           // 128 threads, 128 floats
        CP_WAIT0();
    }
    __syncthreads();

    const int nbase = wid * 32;           // warp's 32 output cols

    // ldmatrix per-lane addressing (tile-invariant)
    const int lrow = lane & 15;
    const int lhalf = lane >> 4;
    const int lsw = lrow & 7;
    const uint32_t rowA = (uint32_t)lrow * 128;
    const uint32_t rowB = (uint32_t)(nbase + lrow) * 128;
    uint32_t kc[4];
    #pragma unroll
    for (int kb = 0; kb < 4; kb++)
        kc[kb] = (uint32_t)(((kb * 2 + lhalf) ^ lsw) * 16);

    const int g = lane >> 2;
    const int n2 = (lane & 3) * 2;

    for (int i = 0; i < cnt; i++) {
        const int tile = start + i;
        const int x0 = (tile & 127) * 64;
        const int y0 = (tile >> 7) * 128;

        float acc[4][4][4];
        #pragma unroll
        for (int mt = 0; mt < 4; mt++)
            #pragma unroll
            for (int nt = 0; nt < 4; nt++)
                #pragma unroll
                for (int f = 0; f < 4; f++)
                    acc[mt][nt][f] = 0.0f;

        // ---- mainloop over K (4 chunks of 16) x 3 terms ----
        #pragma unroll
        for (int kb = 0; kb < 4; kb++) {
            const uint32_t k = kc[kb];
            uint32_t bh[2][4], bl[2][4], ah[4][4], al[4][4];
            #pragma unroll
            for (int bp = 0; bp < 2; bp++) {
                ldsm_x4(bh[bp][0], bh[bp][1], bh[bp][2], bh[bp][3],
                        sY + rowB + bp * 2048 + k);
                ldsm_x4(bl[bp][0], bl[bp][1], bl[bp][2], bl[bp][3],
                        sY + YT_BYTES + rowB + bp * 2048 + k);
            }
            #pragma unroll
            for (int mt = 0; mt < 4; mt++)
                ldsm_x4(ah[mt][0], ah[mt][1], ah[mt][2], ah[mt][3],
                        sX + rowA + mt * 2048 + k);

            // term hi*hi
            #pragma unroll
            for (int mt = 0; mt < 4; mt++) {
                mma_bf16(acc[mt][0], ah[mt], bh[0][0], bh[0][2]);
                mma_bf16(acc[mt][1], ah[mt], bh[0][1], bh[0][3]);
                mma_bf16(acc[mt][2], ah[mt], bh[1][0], bh[1][2]);
                mma_bf16(acc[mt][3], ah[mt], bh[1][1], bh[1][3]);
            }
            // load A-lo while hi*lo MMAs run
            #pragma unroll
            for (int mt = 0; mt < 4; mt++)
                ldsm_x4(al[mt][0], al[mt][1], al[mt][2], al[mt][3],
                        sX + XT_BYTES + rowA + mt * 2048 + k);
            // term hi*lo
            #pragma unroll
            for (int mt = 0; mt < 4; mt++) {
                mma_bf16(acc[mt][0], ah[mt], bl[0][0], bl[0][2]);
                mma_bf16(acc[mt][1], ah[mt], bl[0][1], bl[0][3]);
                mma_bf16(acc[mt][2], ah[mt], bl[1][0], bl[1][2]);
                mma_bf16(acc[mt][3], ah[mt], bl[1][1], bl[1][3]);
            }
            // term lo*hi
            #pragma unroll
            for (int mt = 0; mt < 4; mt++) {
                mma_bf16(acc[mt][0], al[mt], bh[0][0], bh[0][2]);
                mma_bf16(acc[mt][1], al[mt], bh[0][1], bh[0][3]);
                mma_bf16(acc[mt][2], al[mt], bh[1][0], bh[1][2]);
                mma_bf16(acc[mt][3], al[mt], bh[1][1], bh[1][3]);
            }
        }

        // All warps past their LDSMs for this tile -> X/Y buffers reusable.
        __syncthreads();

        const bool more = (i + 1 < cnt);
        bool newY = false;
        if (more) {
            const int tn = tile + 1;
            newY = (tn >> 7) != (tile >> 7);
            load_x_tile(sX, (tn & 127) * 64, t);
            if (newY) load_y_tile(sY, (tn >> 7) * 128, t);
            CP_COMMIT();
        }

        // ---- epilogue: out = exp2(cross*L2E - hx' - hy') ----
        // hx' = hx*L2E - log2(v) (read from L2-hot global), hy' = HY smem.
        // d2 >= 0 analytically; split error ~3e-5 -> no clamp needed.
        #pragma unroll
        for (int mt = 0; mt < 4; mt++) {
            const int r0 = mt * 16 + g;
            const float hx0 = fmaf(g_hxn[x0 + r0],     L2E, -lv);
            const float hx1 = fmaf(g_hxn[x0 + r0 + 8], L2E, -lv);
            #pragma unroll
            for (int nt = 0; nt < 4; nt++) {
                const int cc = nbase + nt * 8 + n2;
                const float hy0 = HY[cc];
                const float hy1 = HY[cc + 1];
                float* c = acc[mt][nt];
                float2 o0, o1;
                o0.x = fexp2(fmaf(c[0], L2E, -hx0 - hy0));
                o0.y = fexp2(fmaf(c[1], L2E, -hx0 - hy1));
                o1.x = fexp2(fmaf(c[2], L2E, -hx1 - hy0));
                o1.y = fexp2(fmaf(c[3], L2E, -hx1 - hy1));
                *(float2*)(out + (size_t)(x0 + r0) * MROWS + y0 + cc)     = o0;
                *(float2*)(out + (size_t)(x0 + r0 + 8) * MROWS + y0 + cc) = o1;
            }
        }

        if (more) {
            CP_WAIT0();
            if (newY) {
                __syncthreads();   // everyone done reading old HY
                HY[t] = g_hyn[((tile + 1) >> 7) * 128 + t] * L2E;
            }
            __syncthreads();
        }
    }
}

// ---------------------------------------------------------------------------
extern "C" void kernel_launch(void* const* d_in, const int* in_sizes, int n_in,
                              void* d_out, int out_size) {
    const float* X   = (const float*)d_in[0];
    const float* X2  = (const float*)d_in[1];
    const float* ls  = (const float*)d_in[2];
    const float* var = (const float*)d_in[3];
    float* out = (float*)d_out;

    prep_kernel<<<1024, 256>>>(X, X2, ls, var);

    cudaFuncSetAttribute(rbf_mma_kernel,
                         cudaFuncAttributeMaxDynamicSharedMemorySize, SMEM_TOTAL);
    rbf_mma_kernel<<<NCTAS, 128, SMEM_TOTAL>>>(out);
}